// round 2
// baseline (speedup 1.0000x reference)
#include <cuda_runtime.h>
#include <math.h>

// Problem constants (fixed shapes)
#define BATCH 1024
#define HW 49
#define NN (BATCH*HW)        // 50176
#define INDIM 1024
#define HIDD 512
#define EPB 84               // edges per batch: 42 horizontal + 42 vertical
#define EE (BATCH*EPB)       // 86016
#define EDGE_BLOCKS 336      // EE / 256
#define STAT_BLOCKS 512

// Scratch (static device globals; no allocations allowed)
__device__ float g_node[(size_t)NN*INDIM];   // node features [N,1024]; reused as decoder output [N,512]
__device__ float g_agg [(size_t)NN*INDIM];   // aggregated neighbor features
__device__ float g_h1  [(size_t)NN*HIDD];
__device__ float g_h2  [(size_t)NN*HIDD];
__device__ float g_coords[NN*2];
__device__ float g_ea  [EE];                 // sigmoid edge attr
__device__ float g_alpha[EE];                // exp(ea) then normalized alpha
__device__ float g_nodew[NN];
__device__ float g_epart[EDGE_BLOCKS];
__device__ float g_sumexp[1];
__device__ float g_psum[STAT_BLOCKS*HIDD];
__device__ float g_psq [STAT_BLOCKS*HIDD];
__device__ float g_scale[HIDD];
__device__ float g_shift[HIDD];

// ---------------------------------------------------------------------------
// K1: NCHW concat -> [N, 1024] row-major node matrix (smem transpose)
// blockIdx: b*8 + t, t selects 128-channel tile (t<4: visual, else tactile)
__global__ void k_build_node(const float* __restrict__ vis,
                             const float* __restrict__ tac,
                             float* __restrict__ node) {
    int b = blockIdx.x >> 3;
    int t = blockIdx.x & 7;
    const float* src = (t < 4) ? vis : tac;
    __shared__ float tile[128*49];
    const float* p = src + ((size_t)b*512 + (size_t)(t & 3)*128) * 49;
    for (int i = threadIdx.x; i < 128*49; i += 256) tile[i] = p[i];   // fully contiguous read
    __syncthreads();
    for (int i = threadIdx.x; i < 128*49; i += 256) {
        int pos = i >> 7, ch = i & 127;
        node[((size_t)(b*HW + pos))*INDIM + t*128 + ch] = tile[ch*49 + pos]; // stride-49 smem: conflict-free
    }
}

// ---------------------------------------------------------------------------
// K2: coords = node @ proj_W + proj_b   ([N,1024] @ [1024,2])
__global__ void k_coords(const float* __restrict__ node,
                         const float* __restrict__ pW,
                         const float* __restrict__ pb,
                         float* __restrict__ coords) {
    __shared__ float sW[INDIM*2];
    for (int i = threadIdx.x; i < INDIM*2; i += 256) sW[i] = pW[i];
    __syncthreads();
    int warp = threadIdx.x >> 5, lane = threadIdx.x & 31;
    int n = blockIdx.x*8 + warp;
    const float4* row = reinterpret_cast<const float4*>(node + (size_t)n*INDIM);
    float c0 = 0.f, c1 = 0.f;
    for (int k = lane; k < INDIM/4; k += 32) {
        float4 v = row[k];
        const float* w = &sW[k*8];
        c0 += v.x*w[0] + v.y*w[2] + v.z*w[4] + v.w*w[6];
        c1 += v.x*w[1] + v.y*w[3] + v.z*w[5] + v.w*w[7];
    }
    #pragma unroll
    for (int o = 16; o; o >>= 1) {
        c0 += __shfl_down_sync(0xffffffffu, c0, o);
        c1 += __shfl_down_sync(0xffffffffu, c1, o);
    }
    if (lane == 0) { coords[2*n] = c0 + pb[0]; coords[2*n+1] = c1 + pb[1]; }
}

// ---------------------------------------------------------------------------
// K3: per-edge attr + exp, with per-block partial sums (deterministic)
// Edge layout per batch: k<42 horizontal (r*6+c : (r,c)->(r,c+1)),
//                        k>=42 vertical  (42 + r*7+c : (r,c)->(r+1,c))
__global__ void k_edge(const float* __restrict__ coords,
                       float* __restrict__ ea,
                       float* __restrict__ ex,
                       float* __restrict__ epart) {
    int e = blockIdx.x*256 + threadIdx.x;
    float v = 0.f;
    {
        int b = e / EPB, k = e % EPB;
        int s, d;
        if (k < 42) { int r = k/6, c = k%6; s = r*7+c; d = s+1; }
        else        { int k2 = k-42; int r = k2/7, c = k2%7; s = r*7+c; d = s+7; }
        s += b*HW; d += b*HW;
        float dx = coords[2*s]   - coords[2*d];
        float dy = coords[2*s+1] - coords[2*d+1];
        float dist = sqrtf(dx*dx + dy*dy);
        float a = 1.f / (1.f + expf(-(1.f/(dist + 1e-6f))));  // sigmoid(1/(dist+eps))
        ea[e] = a;
        v = expf(a);
        ex[e] = v;
    }
    __shared__ float red[8];
    #pragma unroll
    for (int o = 16; o; o >>= 1) v += __shfl_down_sync(0xffffffffu, v, o);
    if ((threadIdx.x & 31) == 0) red[threadIdx.x >> 5] = v;
    __syncthreads();
    if (threadIdx.x < 8) {
        float s = red[threadIdx.x];
        #pragma unroll
        for (int o = 4; o; o >>= 1) s += __shfl_down_sync(0xffu, s, o);
        if (threadIdx.x == 0) epart[blockIdx.x] = s;
    }
}

__global__ void k_sumexp(const float* __restrict__ epart, float* __restrict__ out) {
    int t = threadIdx.x;  // 512 threads
    float v = (t < EDGE_BLOCKS) ? epart[t] : 0.f;
    __shared__ float red[16];
    #pragma unroll
    for (int o = 16; o; o >>= 1) v += __shfl_down_sync(0xffffffffu, v, o);
    if ((t & 31) == 0) red[t >> 5] = v;
    __syncthreads();
    if (t < 16) {
        float s = red[t];
        #pragma unroll
        for (int o = 8; o; o >>= 1) s += __shfl_down_sync(0xffffu, s, o);
        if (t == 0) out[0] = s;
    }
}

__global__ void k_alpha(float* __restrict__ ex, const float* __restrict__ sumexp) {
    int e = blockIdx.x*256 + threadIdx.x;
    float inv = 1.f / (sumexp[0] + 1e-8f);
    ex[e] = ex[e] * inv;
}

// scatter_mean of ea over both endpoints, closed form on the grid
__global__ void k_nodew(const float* __restrict__ ea, float* __restrict__ nw) {
    int n = blockIdx.x*256 + threadIdx.x;
    int b = n / HW, pos = n % HW, r = pos / 7, c = pos % 7;
    const float* base = ea + b*EPB;
    float s = 0.f; int cnt = 0;
    if (c > 0) { s += base[r*6 + (c-1)];     cnt++; }
    if (c < 6) { s += base[r*6 + c];         cnt++; }
    if (r > 0) { s += base[42 + (r-1)*7 + c]; cnt++; }
    if (r < 6) { s += base[42 + r*7 + c];     cnt++; }
    nw[n] = s / (float)cnt;
}

// ---------------------------------------------------------------------------
// K4: neighbor aggregation (closed form: <=2 incoming edges per node)
__global__ void k_agg(const float* __restrict__ x,
                      const float* __restrict__ alpha,
                      float* __restrict__ out, int D4) {
    int idx = blockIdx.x*256 + threadIdx.x;
    int n = idx / D4, j = idx % D4;
    int b = n / HW, pos = n % HW, r = pos / 7, c = pos % 7;
    const float4* x4 = reinterpret_cast<const float4*>(x);
    float4 acc = make_float4(0.f, 0.f, 0.f, 0.f);
    int deg = 0;
    if (c > 0) {
        float a = alpha[b*EPB + r*6 + (c-1)];
        float4 v = x4[(size_t)(n-1)*D4 + j];
        acc.x += a*v.x; acc.y += a*v.y; acc.z += a*v.z; acc.w += a*v.w;
        deg++;
    }
    if (r > 0) {
        float a = alpha[b*EPB + 42 + (r-1)*7 + c];
        float4 v = x4[(size_t)(n-7)*D4 + j];
        acc.x += a*v.x; acc.y += a*v.y; acc.z += a*v.z; acc.w += a*v.w;
        deg++;
    }
    float inv = 1.f / (float)(deg > 0 ? deg : 1);
    acc.x *= inv; acc.y *= inv; acc.z *= inv; acc.w *= inv;
    reinterpret_cast<float4*>(out)[(size_t)n*D4 + j] = acc;
}

// ---------------------------------------------------------------------------
// SGEMM core: C[M,512] = A0@W0 + A1@W1 + bias. 128x128 tile, BK=8, 8x8/thread.
__global__ __launch_bounds__(256)
void k_gemm_dual(const float* __restrict__ A0, const float* __restrict__ W0,
                 const float* __restrict__ A1, const float* __restrict__ W1,
                 const float* __restrict__ bias, float* __restrict__ C, int Kdim) {
    const int Ncols = HIDD;
    __shared__ float As[8][128];
    __shared__ float Bs[8][128];
    int tid = threadIdx.x;
    int tx = tid & 15, ty = tid >> 4;
    int rowBase = blockIdx.y * 128;
    int colBase = blockIdx.x * 128;
    int lr  = tid >> 1;
    int seg = (tid & 1) << 2;
    int bk  = tid >> 5;
    int bc  = (tid & 31) << 2;
    float acc[8][8];
    #pragma unroll
    for (int i = 0; i < 8; i++)
        #pragma unroll
        for (int j = 0; j < 8; j++) acc[i][j] = 0.f;

    for (int pass = 0; pass < 2; ++pass) {
        const float* A = pass ? A1 : A0;
        const float* W = pass ? W1 : W0;
        for (int k0 = 0; k0 < Kdim; k0 += 8) {
            float4 va = *reinterpret_cast<const float4*>(A + (size_t)(rowBase + lr)*Kdim + k0 + seg);
            As[seg+0][lr] = va.x; As[seg+1][lr] = va.y; As[seg+2][lr] = va.z; As[seg+3][lr] = va.w;
            *reinterpret_cast<float4*>(&Bs[bk][bc]) =
                *reinterpret_cast<const float4*>(W + (size_t)(k0 + bk)*Ncols + colBase + bc);
            __syncthreads();
            #pragma unroll
            for (int kk = 0; kk < 8; ++kk) {
                float4 a0 = *reinterpret_cast<const float4*>(&As[kk][ty*8]);
                float4 a1 = *reinterpret_cast<const float4*>(&As[kk][ty*8+4]);
                float4 b0 = *reinterpret_cast<const float4*>(&Bs[kk][tx*8]);
                float4 b1 = *reinterpret_cast<const float4*>(&Bs[kk][tx*8+4]);
                float ra[8] = {a0.x,a0.y,a0.z,a0.w,a1.x,a1.y,a1.z,a1.w};
                float rb[8] = {b0.x,b0.y,b0.z,b0.w,b1.x,b1.y,b1.z,b1.w};
                #pragma unroll
                for (int i = 0; i < 8; i++)
                    #pragma unroll
                    for (int j = 0; j < 8; j++)
                        acc[i][j] = fmaf(ra[i], rb[j], acc[i][j]);
            }
            __syncthreads();
        }
    }
    #pragma unroll
    for (int i = 0; i < 8; i++) {
        size_t row = rowBase + ty*8 + i;
        float* crow = C + row*Ncols + colBase + tx*8;
        float4 o0, o1;
        o0.x = acc[i][0] + bias[colBase + tx*8 + 0];
        o0.y = acc[i][1] + bias[colBase + tx*8 + 1];
        o0.z = acc[i][2] + bias[colBase + tx*8 + 2];
        o0.w = acc[i][3] + bias[colBase + tx*8 + 3];
        o1.x = acc[i][4] + bias[colBase + tx*8 + 4];
        o1.y = acc[i][5] + bias[colBase + tx*8 + 5];
        o1.z = acc[i][6] + bias[colBase + tx*8 + 6];
        o1.w = acc[i][7] + bias[colBase + tx*8 + 7];
        *reinterpret_cast<float4*>(crow)     = o0;
        *reinterpret_cast<float4*>(crow + 4) = o1;
    }
}

// Decoder GEMM: Y = relu(X@W[0:512] + nodew*W[512] + bias), row-major out.
__global__ __launch_bounds__(256)
void k_gemm_dec(const float* __restrict__ A, const float* __restrict__ W,
                const float* __restrict__ nodew, const float* __restrict__ bias,
                float* __restrict__ Y) {
    const int Ncols = HIDD, Kdim = HIDD;
    __shared__ float As[8][128];
    __shared__ float Bs[8][128];
    int tid = threadIdx.x;
    int tx = tid & 15, ty = tid >> 4;
    int rowBase = blockIdx.y * 128;
    int colBase = blockIdx.x * 128;
    int lr  = tid >> 1;
    int seg = (tid & 1) << 2;
    int bk  = tid >> 5;
    int bc  = (tid & 31) << 2;
    float acc[8][8];
    #pragma unroll
    for (int i = 0; i < 8; i++)
        #pragma unroll
        for (int j = 0; j < 8; j++) acc[i][j] = 0.f;

    for (int k0 = 0; k0 < Kdim; k0 += 8) {
        float4 va = *reinterpret_cast<const float4*>(A + (size_t)(rowBase + lr)*Kdim + k0 + seg);
        As[seg+0][lr] = va.x; As[seg+1][lr] = va.y; As[seg+2][lr] = va.z; As[seg+3][lr] = va.w;
        *reinterpret_cast<float4*>(&Bs[bk][bc]) =
            *reinterpret_cast<const float4*>(W + (size_t)(k0 + bk)*Ncols + colBase + bc);
        __syncthreads();
        #pragma unroll
        for (int kk = 0; kk < 8; ++kk) {
            float4 a0 = *reinterpret_cast<const float4*>(&As[kk][ty*8]);
            float4 a1 = *reinterpret_cast<const float4*>(&As[kk][ty*8+4]);
            float4 b0 = *reinterpret_cast<const float4*>(&Bs[kk][tx*8]);
            float4 b1 = *reinterpret_cast<const float4*>(&Bs[kk][tx*8+4]);
            float ra[8] = {a0.x,a0.y,a0.z,a0.w,a1.x,a1.y,a1.z,a1.w};
            float rb[8] = {b0.x,b0.y,b0.z,b0.w,b1.x,b1.y,b1.z,b1.w};
            #pragma unroll
            for (int i = 0; i < 8; i++)
                #pragma unroll
                for (int j = 0; j < 8; j++)
                    acc[i][j] = fmaf(ra[i], rb[j], acc[i][j]);
        }
        __syncthreads();
    }
    const float* wlast = W + (size_t)HIDD * Ncols;  // row 512 of dec_W
    #pragma unroll
    for (int i = 0; i < 8; i++) {
        size_t row = rowBase + ty*8 + i;
        float nwv = nodew[row];
        float* crow = Y + row*Ncols + colBase + tx*8;
        #pragma unroll
        for (int j = 0; j < 8; j += 4) {
            float4 o;
            int col = colBase + tx*8 + j;
            o.x = fmaxf(acc[i][j+0] + nwv*wlast[col+0] + bias[col+0], 0.f);
            o.y = fmaxf(acc[i][j+1] + nwv*wlast[col+1] + bias[col+1], 0.f);
            o.z = fmaxf(acc[i][j+2] + nwv*wlast[col+2] + bias[col+2], 0.f);
            o.w = fmaxf(acc[i][j+3] + nwv*wlast[col+3] + bias[col+3], 0.f);
            *reinterpret_cast<float4*>(crow + j) = o;
        }
    }
}

// ---------------------------------------------------------------------------
// BN stats: deterministic two-stage column sum/sumsq
__global__ void k_colstat(const float* __restrict__ h,
                          float* __restrict__ psum, float* __restrict__ psq) {
    int t = threadIdx.x;           // 256
    int blk = blockIdx.x;          // 512
    const int rows = NN / STAT_BLOCKS;  // 98
    int r0 = blk * rows;
    float s0 = 0.f, q0 = 0.f, s1 = 0.f, q1 = 0.f;
    for (int r = r0; r < r0 + rows; ++r) {
        float v0 = h[(size_t)r*HIDD + t];
        float v1 = h[(size_t)r*HIDD + 256 + t];
        s0 += v0; q0 += v0*v0; s1 += v1; q1 += v1*v1;
    }
    psum[blk*HIDD + t] = s0; psum[blk*HIDD + 256 + t] = s1;
    psq [blk*HIDD + t] = q0; psq [blk*HIDD + 256 + t] = q1;
}

__global__ void k_colfinish(const float* __restrict__ psum, const float* __restrict__ psq,
                            const float* __restrict__ gamma, const float* __restrict__ beta,
                            float* __restrict__ scale, float* __restrict__ shift) {
    int c = threadIdx.x;  // 512
    float s = 0.f, q = 0.f;
    for (int j = 0; j < STAT_BLOCKS; j++) { s += psum[j*HIDD + c]; q += psq[j*HIDD + c]; }
    float mean = s / (float)NN;
    float var  = q / (float)NN - mean*mean;
    float sc = gamma[c] * rsqrtf(var + 1e-5f);
    scale[c] = sc;
    shift[c] = beta[c] - mean*sc;
}

__global__ void k_bnrelu(float* __restrict__ h,
                         const float* __restrict__ scale, const float* __restrict__ shift) {
    int idx = blockIdx.x*256 + threadIdx.x;  // over NN*128 float4s
    float4 v = reinterpret_cast<float4*>(h)[idx];
    int c = (idx & 127) << 2;
    v.x = fmaxf(fmaf(v.x, scale[c+0], shift[c+0]), 0.f);
    v.y = fmaxf(fmaf(v.y, scale[c+1], shift[c+1]), 0.f);
    v.z = fmaxf(fmaf(v.z, scale[c+2], shift[c+2]), 0.f);
    v.w = fmaxf(fmaf(v.w, scale[c+3], shift[c+3]), 0.f);
    reinterpret_cast<float4*>(h)[idx] = v;
}

// ---------------------------------------------------------------------------
// Output transpose: y[N,512] -> out[B,512,7,7]
__global__ void k_out(const float* __restrict__ y, float* __restrict__ out) {
    int b = blockIdx.x >> 2;
    int t = blockIdx.x & 3;  // 128-channel tile
    __shared__ float tile[49*129];
    for (int i = threadIdx.x; i < 49*128; i += 256) {
        int pos = i >> 7, ch = i & 127;
        tile[pos*129 + ch] = y[((size_t)(b*HW + pos))*HIDD + t*128 + ch];
    }
    __syncthreads();
    for (int i = threadIdx.x; i < 49*128; i += 256) {
        int ch = i / 49, pos = i % 49;
        out[((size_t)(b*512) + t*128 + ch)*HW + pos] = tile[pos*129 + ch];
    }
}

// ---------------------------------------------------------------------------
extern "C" void kernel_launch(void* const* d_in, const int* in_sizes, int n_in,
                              void* d_out, int out_size) {
    const float* vis     = (const float*)d_in[0];
    const float* tac     = (const float*)d_in[1];
    const float* projW   = (const float*)d_in[2];
    const float* projb   = (const float*)d_in[3];
    const float* g1relW  = (const float*)d_in[4];
    const float* g1relb  = (const float*)d_in[5];
    const float* g1rootW = (const float*)d_in[6];
    const float* bn1g    = (const float*)d_in[7];
    const float* bn1b    = (const float*)d_in[8];
    const float* g2relW  = (const float*)d_in[9];
    const float* g2relb  = (const float*)d_in[10];
    const float* g2rootW = (const float*)d_in[11];
    const float* bn2g    = (const float*)d_in[12];
    const float* bn2b    = (const float*)d_in[13];
    const float* decW    = (const float*)d_in[14];
    const float* decb    = (const float*)d_in[15];
    float* out = (float*)d_out;

    float *node, *agg, *h1, *h2, *coords, *ea, *alpha, *nodew, *epart, *sumexp;
    float *psum, *psq, *scale, *shift;
    cudaGetSymbolAddress((void**)&node,   g_node);
    cudaGetSymbolAddress((void**)&agg,    g_agg);
    cudaGetSymbolAddress((void**)&h1,     g_h1);
    cudaGetSymbolAddress((void**)&h2,     g_h2);
    cudaGetSymbolAddress((void**)&coords, g_coords);
    cudaGetSymbolAddress((void**)&ea,     g_ea);
    cudaGetSymbolAddress((void**)&alpha,  g_alpha);
    cudaGetSymbolAddress((void**)&nodew,  g_nodew);
    cudaGetSymbolAddress((void**)&epart,  g_epart);
    cudaGetSymbolAddress((void**)&sumexp, g_sumexp);
    cudaGetSymbolAddress((void**)&psum,   g_psum);
    cudaGetSymbolAddress((void**)&psq,    g_psq);
    cudaGetSymbolAddress((void**)&scale,  g_scale);
    cudaGetSymbolAddress((void**)&shift,  g_shift);

    dim3 gg(HIDD/128, NN/128);  // (4, 392)

    k_build_node<<<BATCH*8, 256>>>(vis, tac, node);
    k_coords<<<NN/8, 256>>>(node, projW, projb, coords);
    k_edge<<<EDGE_BLOCKS, 256>>>(coords, ea, alpha, epart);
    k_sumexp<<<1, 512>>>(epart, sumexp);
    k_alpha<<<EDGE_BLOCKS, 256>>>(alpha, sumexp);
    k_nodew<<<NN/256, 256>>>(ea, nodew);

    // GC1
    k_agg<<<NN, 256>>>(node, alpha, agg, INDIM/4);
    k_gemm_dual<<<gg, 256>>>(agg, g1relW, node, g1rootW, g1relb, h1, INDIM);
    k_colstat<<<STAT_BLOCKS, 256>>>(h1, psum, psq);
    k_colfinish<<<1, 512>>>(psum, psq, bn1g, bn1b, scale, shift);
    k_bnrelu<<<NN*128/256, 256>>>(h1, scale, shift);

    // GC2
    k_agg<<<NN/2, 256>>>(h1, alpha, agg, HIDD/4);
    k_gemm_dual<<<gg, 256>>>(agg, g2relW, h1, g2rootW, g2relb, h2, HIDD);
    k_colstat<<<STAT_BLOCKS, 256>>>(h2, psum, psq);
    k_colfinish<<<1, 512>>>(psum, psq, bn2g, bn2b, scale, shift);
    k_bnrelu<<<NN*128/256, 256>>>(h2, scale, shift);

    // Decoder (+rank-1 node_w term) -> reuse g_node as y buffer
    k_gemm_dec<<<gg, 256>>>(h2, decW, nodew, decb, node);
    k_out<<<BATCH*4, 256>>>(node, out);
}

// round 3
// speedup vs baseline: 2.2433x; 2.2433x over previous
#include <cuda_runtime.h>
#include <math.h>

// Problem constants (fixed shapes)
#define BATCH 1024
#define HW 49
#define NN (BATCH*HW)        // 50176
#define INDIM 1024
#define HIDD 512
#define EPB 84               // edges per batch: 42 horizontal + 42 vertical
#define EE (BATCH*EPB)       // 86016
#define EDGE_BLOCKS 336      // EE / 256
#define STAT_BLOCKS 512

// Scratch (static device globals; no allocations allowed)
__device__ float g_node[(size_t)NN*INDIM];
__device__ float g_agg [(size_t)NN*INDIM];
__device__ float g_h1  [(size_t)NN*HIDD];
__device__ float g_h2  [(size_t)NN*HIDD];
__device__ float g_coords[NN*2];
__device__ float g_ea  [EE];
__device__ float g_alpha[EE];
__device__ float g_nodew[NN];
__device__ float g_epart[EDGE_BLOCKS];
__device__ float g_sumexp[1];
__device__ float g_psum[STAT_BLOCKS*HIDD];
__device__ float g_psq [STAT_BLOCKS*HIDD];
__device__ float g_scale[HIDD];
__device__ float g_shift[HIDD];

__device__ __forceinline__ unsigned f2tf(float f) {
    unsigned u; asm("cvt.rna.tf32.f32 %0, %1;" : "=r"(u) : "f"(f)); return u;
}

// ---------------------------------------------------------------------------
// K1: NCHW concat -> [N, 1024] row-major node matrix (smem transpose)
__global__ void k_build_node(const float* __restrict__ vis,
                             const float* __restrict__ tac,
                             float* __restrict__ node) {
    int b = blockIdx.x >> 3;
    int t = blockIdx.x & 7;
    const float* src = (t < 4) ? vis : tac;
    __shared__ float tile[128*49];
    const float* p = src + ((size_t)b*512 + (size_t)(t & 3)*128) * 49;
    for (int i = threadIdx.x; i < 128*49; i += 256) tile[i] = p[i];
    __syncthreads();
    for (int i = threadIdx.x; i < 128*49; i += 256) {
        int pos = i >> 7, ch = i & 127;
        node[((size_t)(b*HW + pos))*INDIM + t*128 + ch] = tile[ch*49 + pos];
    }
}

// ---------------------------------------------------------------------------
// K2: coords = node @ proj_W + proj_b
__global__ void k_coords(const float* __restrict__ node,
                         const float* __restrict__ pW,
                         const float* __restrict__ pb,
                         float* __restrict__ coords) {
    __shared__ float sW[INDIM*2];
    for (int i = threadIdx.x; i < INDIM*2; i += 256) sW[i] = pW[i];
    __syncthreads();
    int warp = threadIdx.x >> 5, lane = threadIdx.x & 31;
    int n = blockIdx.x*8 + warp;
    const float4* row = reinterpret_cast<const float4*>(node + (size_t)n*INDIM);
    float c0 = 0.f, c1 = 0.f;
    for (int k = lane; k < INDIM/4; k += 32) {
        float4 v = row[k];
        const float* w = &sW[k*8];
        c0 += v.x*w[0] + v.y*w[2] + v.z*w[4] + v.w*w[6];
        c1 += v.x*w[1] + v.y*w[3] + v.z*w[5] + v.w*w[7];
    }
    #pragma unroll
    for (int o = 16; o; o >>= 1) {
        c0 += __shfl_down_sync(0xffffffffu, c0, o);
        c1 += __shfl_down_sync(0xffffffffu, c1, o);
    }
    if (lane == 0) { coords[2*n] = c0 + pb[0]; coords[2*n+1] = c1 + pb[1]; }
}

// ---------------------------------------------------------------------------
// K3: per-edge attr + exp, per-block partial sums (deterministic)
__global__ void k_edge(const float* __restrict__ coords,
                       float* __restrict__ ea,
                       float* __restrict__ ex,
                       float* __restrict__ epart) {
    int e = blockIdx.x*256 + threadIdx.x;
    float v = 0.f;
    {
        int b = e / EPB, k = e % EPB;
        int s, d;
        if (k < 42) { int r = k/6, c = k%6; s = r*7+c; d = s+1; }
        else        { int k2 = k-42; int r = k2/7, c = k2%7; s = r*7+c; d = s+7; }
        s += b*HW; d += b*HW;
        float dx = coords[2*s]   - coords[2*d];
        float dy = coords[2*s+1] - coords[2*d+1];
        float dist = sqrtf(dx*dx + dy*dy);
        float a = 1.f / (1.f + expf(-(1.f/(dist + 1e-6f))));
        ea[e] = a;
        v = expf(a);
        ex[e] = v;
    }
    __shared__ float red[8];
    #pragma unroll
    for (int o = 16; o; o >>= 1) v += __shfl_down_sync(0xffffffffu, v, o);
    if ((threadIdx.x & 31) == 0) red[threadIdx.x >> 5] = v;
    __syncthreads();
    if (threadIdx.x < 8) {
        float s = red[threadIdx.x];
        #pragma unroll
        for (int o = 4; o; o >>= 1) s += __shfl_down_sync(0xffu, s, o);
        if (threadIdx.x == 0) epart[blockIdx.x] = s;
    }
}

__global__ void k_sumexp(const float* __restrict__ epart, float* __restrict__ out) {
    int t = threadIdx.x;
    float v = (t < EDGE_BLOCKS) ? epart[t] : 0.f;
    __shared__ float red[16];
    #pragma unroll
    for (int o = 16; o; o >>= 1) v += __shfl_down_sync(0xffffffffu, v, o);
    if ((t & 31) == 0) red[t >> 5] = v;
    __syncthreads();
    if (t < 16) {
        float s = red[t];
        #pragma unroll
        for (int o = 8; o; o >>= 1) s += __shfl_down_sync(0xffffu, s, o);
        if (t == 0) out[0] = s;
    }
}

__global__ void k_alpha(float* __restrict__ ex, const float* __restrict__ sumexp) {
    int e = blockIdx.x*256 + threadIdx.x;
    float inv = 1.f / (sumexp[0] + 1e-8f);
    ex[e] = ex[e] * inv;
}

__global__ void k_nodew(const float* __restrict__ ea, float* __restrict__ nw) {
    int n = blockIdx.x*256 + threadIdx.x;
    int b = n / HW, pos = n % HW, r = pos / 7, c = pos % 7;
    const float* base = ea + b*EPB;
    float s = 0.f; int cnt = 0;
    if (c > 0) { s += base[r*6 + (c-1)];     cnt++; }
    if (c < 6) { s += base[r*6 + c];         cnt++; }
    if (r > 0) { s += base[42 + (r-1)*7 + c]; cnt++; }
    if (r < 6) { s += base[42 + r*7 + c];     cnt++; }
    nw[n] = s / (float)cnt;
}

// ---------------------------------------------------------------------------
// K4: neighbor aggregation (closed form: <=2 incoming edges per node)
__global__ void k_agg(const float* __restrict__ x,
                      const float* __restrict__ alpha,
                      float* __restrict__ out, int D4) {
    int idx = blockIdx.x*256 + threadIdx.x;
    int n = idx / D4, j = idx % D4;
    int b = n / HW, pos = n % HW, r = pos / 7, c = pos % 7;
    const float4* x4 = reinterpret_cast<const float4*>(x);
    float4 acc = make_float4(0.f, 0.f, 0.f, 0.f);
    int deg = 0;
    if (c > 0) {
        float a = alpha[b*EPB + r*6 + (c-1)];
        float4 v = x4[(size_t)(n-1)*D4 + j];
        acc.x += a*v.x; acc.y += a*v.y; acc.z += a*v.z; acc.w += a*v.w;
        deg++;
    }
    if (r > 0) {
        float a = alpha[b*EPB + 42 + (r-1)*7 + c];
        float4 v = x4[(size_t)(n-7)*D4 + j];
        acc.x += a*v.x; acc.y += a*v.y; acc.z += a*v.z; acc.w += a*v.w;
        deg++;
    }
    float inv = 1.f / (float)(deg > 0 ? deg : 1);
    acc.x *= inv; acc.y *= inv; acc.z *= inv; acc.w *= inv;
    reinterpret_cast<float4*>(out)[(size_t)n*D4 + j] = acc;
}

// ---------------------------------------------------------------------------
// TF32 tensor-core GEMM core.
// Block: 256 thr (8 warps, 4(M) x 2(N)), tile 128x128, BK=16, double-buffered.
// Each warp: 32x64 via 2x8 mma.m16n8k8 tiles. Accum fp32.
// Computes C = A0@W0 + A1@W1 + bias  (A1/W1 may be null for single-pass).
struct TileRegs { float4 a0, a1, b0, b1; };

__device__ __forceinline__ void g_load(const float* __restrict__ A,
                                       const float* __restrict__ W,
                                       int Kd, int rowBase, int colBase, int kk,
                                       int tid, TileRegs& r) {
    int row = tid >> 2, kq = (tid & 3) << 2;
    r.a0 = *reinterpret_cast<const float4*>(A + (size_t)(rowBase + row)*Kd + kk + kq);
    r.a1 = *reinterpret_cast<const float4*>(A + (size_t)(rowBase + row + 64)*Kd + kk + kq);
    int kr = tid >> 5, nq = (tid & 31) << 2;
    r.b0 = *reinterpret_cast<const float4*>(W + (size_t)(kk + kr)*HIDD + colBase + nq);
    r.b1 = *reinterpret_cast<const float4*>(W + (size_t)(kk + kr + 8)*HIDD + colBase + nq);
}

__device__ __forceinline__ void s_store(unsigned (*As)[132], unsigned (*Bs)[132],
                                        int tid, const TileRegs& r) {
    int row = tid >> 2, kq = (tid & 3) << 2;
    As[kq+0][row] = f2tf(r.a0.x); As[kq+1][row] = f2tf(r.a0.y);
    As[kq+2][row] = f2tf(r.a0.z); As[kq+3][row] = f2tf(r.a0.w);
    As[kq+0][row+64] = f2tf(r.a1.x); As[kq+1][row+64] = f2tf(r.a1.y);
    As[kq+2][row+64] = f2tf(r.a1.z); As[kq+3][row+64] = f2tf(r.a1.w);
    int kr = tid >> 5, nq = (tid & 31) << 2;
    uint4 p0 = make_uint4(f2tf(r.b0.x), f2tf(r.b0.y), f2tf(r.b0.z), f2tf(r.b0.w));
    uint4 p1 = make_uint4(f2tf(r.b1.x), f2tf(r.b1.y), f2tf(r.b1.z), f2tf(r.b1.w));
    *reinterpret_cast<uint4*>(&Bs[kr][nq])     = p0;
    *reinterpret_cast<uint4*>(&Bs[kr+8][nq])   = p1;
}

#define MMA_TF32(d, a, b0v, b1v) \
    asm volatile("mma.sync.aligned.m16n8k8.row.col.f32.tf32.tf32.f32 " \
                 "{%0,%1,%2,%3}, {%4,%5,%6,%7}, {%8,%9}, {%0,%1,%2,%3};" \
                 : "+f"(d[0]), "+f"(d[1]), "+f"(d[2]), "+f"(d[3]) \
                 : "r"(a[0]), "r"(a[1]), "r"(a[2]), "r"(a[3]), "r"(b0v), "r"(b1v))

__device__ __forceinline__ void mma_tile(const unsigned (*As)[132], const unsigned (*Bs)[132],
                                         int wm, int wn, int lane, float acc[2][8][4]) {
    int grp = lane >> 2, tig = lane & 3;
    #pragma unroll
    for (int ks = 0; ks < 16; ks += 8) {
        unsigned ua[2][4];
        #pragma unroll
        for (int mt = 0; mt < 2; mt++) {
            int m = (wm << 5) + (mt << 4) + grp;
            ua[mt][0] = As[ks + tig][m];
            ua[mt][1] = As[ks + tig][m + 8];
            ua[mt][2] = As[ks + tig + 4][m];
            ua[mt][3] = As[ks + tig + 4][m + 8];
        }
        #pragma unroll
        for (int nt = 0; nt < 8; nt++) {
            int n = (wn << 6) + (nt << 3) + grp;
            unsigned b0 = Bs[ks + tig][n];
            unsigned b1 = Bs[ks + tig + 4][n];
            MMA_TF32(acc[0][nt], ua[0], b0, b1);
            MMA_TF32(acc[1][nt], ua[1], b0, b1);
        }
    }
}

__global__ __launch_bounds__(256)
void k_gemm_dual_tf32(const float* __restrict__ A0, const float* __restrict__ W0,
                      const float* __restrict__ A1, const float* __restrict__ W1,
                      const float* __restrict__ bias, float* __restrict__ C, int Kd) {
    __shared__ __align__(16) unsigned As[2][16][132];
    __shared__ __align__(16) unsigned Bs[2][16][132];
    int tid = threadIdx.x;
    int lane = tid & 31, wid = tid >> 5;
    int wm = wid & 3, wn = wid >> 2;
    int rowBase = blockIdx.y * 128, colBase = blockIdx.x * 128;
    int nHalf = Kd >> 4;           // iters per pass
    int niter = nHalf * 2;

    float acc[2][8][4];
    #pragma unroll
    for (int mt = 0; mt < 2; mt++)
        #pragma unroll
        for (int nt = 0; nt < 8; nt++)
            #pragma unroll
            for (int i = 0; i < 4; i++) acc[mt][nt][i] = 0.f;

    TileRegs r;
    g_load(A0, W0, Kd, rowBase, colBase, 0, tid, r);
    s_store(As[0], Bs[0], tid, r);
    __syncthreads();

    int buf = 0;
    for (int iter = 0; iter < niter; ++iter) {
        if (iter + 1 < niter) {
            int nx = iter + 1;
            int pass = nx >= nHalf;
            int kk = (nx - (pass ? nHalf : 0)) << 4;
            g_load(pass ? A1 : A0, pass ? W1 : W0, Kd, rowBase, colBase, kk, tid, r);
        }
        mma_tile(As[buf], Bs[buf], wm, wn, lane, acc);
        if (iter + 1 < niter) {
            s_store(As[buf ^ 1], Bs[buf ^ 1], tid, r);
            __syncthreads();
            buf ^= 1;
        }
    }

    int grp = lane >> 2, tig = lane & 3;
    #pragma unroll
    for (int mt = 0; mt < 2; mt++) {
        #pragma unroll
        for (int nt = 0; nt < 8; nt++) {
            int row = rowBase + (wm << 5) + (mt << 4) + grp;
            int col = colBase + (wn << 6) + (nt << 3) + (tig << 1);
            float2 lo = make_float2(acc[mt][nt][0] + bias[col], acc[mt][nt][1] + bias[col+1]);
            float2 hi = make_float2(acc[mt][nt][2] + bias[col], acc[mt][nt][3] + bias[col+1]);
            *reinterpret_cast<float2*>(C + (size_t)row*HIDD + col)       = lo;
            *reinterpret_cast<float2*>(C + (size_t)(row+8)*HIDD + col)   = hi;
        }
    }
}

// Decoder GEMM: Y = relu(X@W[0:512] + nodew*W[512] + bias)
__global__ __launch_bounds__(256)
void k_gemm_dec_tf32(const float* __restrict__ A, const float* __restrict__ W,
                     const float* __restrict__ nodew, const float* __restrict__ bias,
                     float* __restrict__ Y) {
    const int Kd = HIDD;
    __shared__ __align__(16) unsigned As[2][16][132];
    __shared__ __align__(16) unsigned Bs[2][16][132];
    int tid = threadIdx.x;
    int lane = tid & 31, wid = tid >> 5;
    int wm = wid & 3, wn = wid >> 2;
    int rowBase = blockIdx.y * 128, colBase = blockIdx.x * 128;
    int niter = Kd >> 4;

    float acc[2][8][4];
    #pragma unroll
    for (int mt = 0; mt < 2; mt++)
        #pragma unroll
        for (int nt = 0; nt < 8; nt++)
            #pragma unroll
            for (int i = 0; i < 4; i++) acc[mt][nt][i] = 0.f;

    TileRegs r;
    g_load(A, W, Kd, rowBase, colBase, 0, tid, r);
    s_store(As[0], Bs[0], tid, r);
    __syncthreads();

    int buf = 0;
    for (int iter = 0; iter < niter; ++iter) {
        if (iter + 1 < niter)
            g_load(A, W, Kd, rowBase, colBase, (iter + 1) << 4, tid, r);
        mma_tile(As[buf], Bs[buf], wm, wn, lane, acc);
        if (iter + 1 < niter) {
            s_store(As[buf ^ 1], Bs[buf ^ 1], tid, r);
            __syncthreads();
            buf ^= 1;
        }
    }

    const float* wlast = W + (size_t)HIDD * HIDD;
    int grp = lane >> 2, tig = lane & 3;
    #pragma unroll
    for (int mt = 0; mt < 2; mt++) {
        #pragma unroll
        for (int nt = 0; nt < 8; nt++) {
            int row = rowBase + (wm << 5) + (mt << 4) + grp;
            int col = colBase + (wn << 6) + (nt << 3) + (tig << 1);
            float nw0 = nodew[row], nw1 = nodew[row + 8];
            float w0 = wlast[col], w1 = wlast[col+1];
            float b0 = bias[col], b1 = bias[col+1];
            float2 lo = make_float2(fmaxf(acc[mt][nt][0] + nw0*w0 + b0, 0.f),
                                    fmaxf(acc[mt][nt][1] + nw0*w1 + b1, 0.f));
            float2 hi = make_float2(fmaxf(acc[mt][nt][2] + nw1*w0 + b0, 0.f),
                                    fmaxf(acc[mt][nt][3] + nw1*w1 + b1, 0.f));
            *reinterpret_cast<float2*>(Y + (size_t)row*HIDD + col)     = lo;
            *reinterpret_cast<float2*>(Y + (size_t)(row+8)*HIDD + col) = hi;
        }
    }
}

// ---------------------------------------------------------------------------
// BN stats: deterministic two-stage column sum/sumsq
__global__ void k_colstat(const float* __restrict__ h,
                          float* __restrict__ psum, float* __restrict__ psq) {
    int t = threadIdx.x;
    int blk = blockIdx.x;
    const int rows = NN / STAT_BLOCKS;
    int r0 = blk * rows;
    float s0 = 0.f, q0 = 0.f, s1 = 0.f, q1 = 0.f;
    for (int r = r0; r < r0 + rows; ++r) {
        float v0 = h[(size_t)r*HIDD + t];
        float v1 = h[(size_t)r*HIDD + 256 + t];
        s0 += v0; q0 += v0*v0; s1 += v1; q1 += v1*v1;
    }
    psum[blk*HIDD + t] = s0; psum[blk*HIDD + 256 + t] = s1;
    psq [blk*HIDD + t] = q0; psq [blk*HIDD + 256 + t] = q1;
}

__global__ void k_colfinish(const float* __restrict__ psum, const float* __restrict__ psq,
                            const float* __restrict__ gamma, const float* __restrict__ beta,
                            float* __restrict__ scale, float* __restrict__ shift) {
    int c = threadIdx.x;
    float s = 0.f, q = 0.f;
    for (int j = 0; j < STAT_BLOCKS; j++) { s += psum[j*HIDD + c]; q += psq[j*HIDD + c]; }
    float mean = s / (float)NN;
    float var  = q / (float)NN - mean*mean;
    float sc = gamma[c] * rsqrtf(var + 1e-5f);
    scale[c] = sc;
    shift[c] = beta[c] - mean*sc;
}

__global__ void k_bnrelu(float* __restrict__ h,
                         const float* __restrict__ scale, const float* __restrict__ shift) {
    int idx = blockIdx.x*256 + threadIdx.x;
    float4 v = reinterpret_cast<float4*>(h)[idx];
    int c = (idx & 127) << 2;
    v.x = fmaxf(fmaf(v.x, scale[c+0], shift[c+0]), 0.f);
    v.y = fmaxf(fmaf(v.y, scale[c+1], shift[c+1]), 0.f);
    v.z = fmaxf(fmaf(v.z, scale[c+2], shift[c+2]), 0.f);
    v.w = fmaxf(fmaf(v.w, scale[c+3], shift[c+3]), 0.f);
    reinterpret_cast<float4*>(h)[idx] = v;
}

// ---------------------------------------------------------------------------
// Output transpose: y[N,512] -> out[B,512,7,7]
__global__ void k_out(const float* __restrict__ y, float* __restrict__ out) {
    int b = blockIdx.x >> 2;
    int t = blockIdx.x & 3;
    __shared__ float tile[49*129];
    for (int i = threadIdx.x; i < 49*128; i += 256) {
        int pos = i >> 7, ch = i & 127;
        tile[pos*129 + ch] = y[((size_t)(b*HW + pos))*HIDD + t*128 + ch];
    }
    __syncthreads();
    for (int i = threadIdx.x; i < 49*128; i += 256) {
        int ch = i / 49, pos = i % 49;
        out[((size_t)(b*512) + t*128 + ch)*HW + pos] = tile[pos*129 + ch];
    }
}

// ---------------------------------------------------------------------------
extern "C" void kernel_launch(void* const* d_in, const int* in_sizes, int n_in,
                              void* d_out, int out_size) {
    const float* vis     = (const float*)d_in[0];
    const float* tac     = (const float*)d_in[1];
    const float* projW   = (const float*)d_in[2];
    const float* projb   = (const float*)d_in[3];
    const float* g1relW  = (const float*)d_in[4];
    const float* g1relb  = (const float*)d_in[5];
    const float* g1rootW = (const float*)d_in[6];
    const float* bn1g    = (const float*)d_in[7];
    const float* bn1b    = (const float*)d_in[8];
    const float* g2relW  = (const float*)d_in[9];
    const float* g2relb  = (const float*)d_in[10];
    const float* g2rootW = (const float*)d_in[11];
    const float* bn2g    = (const float*)d_in[12];
    const float* bn2b    = (const float*)d_in[13];
    const float* decW    = (const float*)d_in[14];
    const float* decb    = (const float*)d_in[15];
    float* out = (float*)d_out;

    float *node, *agg, *h1, *h2, *coords, *ea, *alpha, *nodew, *epart, *sumexp;
    float *psum, *psq, *scale, *shift;
    cudaGetSymbolAddress((void**)&node,   g_node);
    cudaGetSymbolAddress((void**)&agg,    g_agg);
    cudaGetSymbolAddress((void**)&h1,     g_h1);
    cudaGetSymbolAddress((void**)&h2,     g_h2);
    cudaGetSymbolAddress((void**)&coords, g_coords);
    cudaGetSymbolAddress((void**)&ea,     g_ea);
    cudaGetSymbolAddress((void**)&alpha,  g_alpha);
    cudaGetSymbolAddress((void**)&nodew,  g_nodew);
    cudaGetSymbolAddress((void**)&epart,  g_epart);
    cudaGetSymbolAddress((void**)&sumexp, g_sumexp);
    cudaGetSymbolAddress((void**)&psum,   g_psum);
    cudaGetSymbolAddress((void**)&psq,    g_psq);
    cudaGetSymbolAddress((void**)&scale,  g_scale);
    cudaGetSymbolAddress((void**)&shift,  g_shift);

    dim3 gg(HIDD/128, NN/128);  // (4, 392)

    k_build_node<<<BATCH*8, 256>>>(vis, tac, node);
    k_coords<<<NN/8, 256>>>(node, projW, projb, coords);
    k_edge<<<EDGE_BLOCKS, 256>>>(coords, ea, alpha, epart);
    k_sumexp<<<1, 512>>>(epart, sumexp);
    k_alpha<<<EDGE_BLOCKS, 256>>>(alpha, sumexp);
    k_nodew<<<NN/256, 256>>>(ea, nodew);

    // GC1
    k_agg<<<NN, 256>>>(node, alpha, agg, INDIM/4);
    k_gemm_dual_tf32<<<gg, 256>>>(agg, g1relW, node, g1rootW, g1relb, h1, INDIM);
    k_colstat<<<STAT_BLOCKS, 256>>>(h1, psum, psq);
    k_colfinish<<<1, 512>>>(psum, psq, bn1g, bn1b, scale, shift);
    k_bnrelu<<<NN*128/256, 256>>>(h1, scale, shift);

    // GC2
    k_agg<<<NN/2, 256>>>(h1, alpha, agg, HIDD/4);
    k_gemm_dual_tf32<<<gg, 256>>>(agg, g2relW, h1, g2rootW, g2relb, h2, HIDD);
    k_colstat<<<STAT_BLOCKS, 256>>>(h2, psum, psq);
    k_colfinish<<<1, 512>>>(psum, psq, bn2g, bn2b, scale, shift);
    k_bnrelu<<<NN*128/256, 256>>>(h2, scale, shift);

    // Decoder (+rank-1 node_w term) -> reuse g_node as y buffer
    k_gemm_dec_tf32<<<gg, 256>>>(h2, decW, nodew, decb, node);
    k_out<<<BATCH*4, 256>>>(node, out);
}